// round 16
// baseline (speedup 1.0000x reference)
#include <cuda_runtime.h>
#include <cuda_fp16.h>
#include <cstdint>

// Problem constants (fixed by the dataset)
#define NN    50000
#define EE    800000
#define IN_F  96
#define HID_F 128
#define OUT_F 64
#define TT    8

#define SCAN_BLK 512
#define NBLK ((NN + SCAN_BLK - 1) / SCAN_BLK)    // 98

// ---------------- static device scratch (no allocations allowed) -------------
__device__ int      g_counts[NN];      // zero-init at load; re-zeroed by k_scan
__device__ int      g_rowptr[NN + 1];
__device__ int      g_cursor[NN];
__device__ int      g_bsum[NBLK];      // sentinel -1 written by k_convert each call
__device__ int2     g_epack[EE];                            // (src, w-as-bits)
__device__ __half   g_xh[(size_t)NN * IN_F];                // 9.6 MB fp16 x
__device__ __half   g_agg1h[(size_t)NN * IN_F];             // 9.6 MB fp16 agg1
__device__ __half   g_ph[(size_t)NN * TT * OUT_F];          // 51.2 MB, [n][t*64+c]
__device__ uint32_t g_B1h[TT * HID_F * 48];                 // fp16x2 [t][n][k2]
__device__ uint32_t g_B2h[TT * OUT_F * 64];                 // fp16x2 [t][n][k2]

// ---------------- helpers ------------------------------------------------------
__device__ __forceinline__ void mma_f16(float d[4],
                                        uint32_t a0, uint32_t a1, uint32_t a2, uint32_t a3,
                                        uint32_t b0, uint32_t b1) {
    asm volatile("mma.sync.aligned.m16n8k16.row.col.f32.f16.f16.f32 "
        "{%0,%1,%2,%3}, {%4,%5,%6,%7}, {%8,%9}, {%0,%1,%2,%3};"
        : "+f"(d[0]), "+f"(d[1]), "+f"(d[2]), "+f"(d[3])
        : "r"(a0), "r"(a1), "r"(a2), "r"(a3), "r"(b0), "r"(b1));
}
__device__ __forceinline__ uint32_t pack_h2(float a, float b) {
    __half2 h = __float22half2_rn(make_float2(a, b));
    return *(uint32_t*)&h;
}

// ---------------- convert + hist + sentinel (fused front-end) ------------------
#define XW4 (NN * IN_F / 4)                // 1,200,000 float4 granules (> EE ok)
__global__ void k_convert(const float* __restrict__ x,
                          const int* __restrict__ dst) {
    int i = blockIdx.x * blockDim.x + threadIdx.x;
    if (i < NBLK) g_bsum[i] = -1;                       // sentinel for k_scan
    if (i < EE) atomicAdd(&g_counts[dst[i]], 1);        // degree histogram
    if (i < XW4) {
        float4 v = ((const float4*)x)[i];
        uint2 o = make_uint2(pack_h2(v.x, v.y), pack_h2(v.z, v.w));
        ((uint2*)g_xh)[i] = o;
    }
}

// ---------------- single-kernel scan (aggregate exchange via sentinel) ---------
__global__ void k_scan() {
    __shared__ int s[SCAN_BLK];
    __shared__ int bs[128];
    int b = blockIdx.x, tid = threadIdx.x;
    int i = b * SCAN_BLK + tid;
    int c = (i < NN) ? g_counts[i] : 0;
    s[tid] = c;
    __syncthreads();
    #pragma unroll
    for (int off = 1; off < SCAN_BLK; off <<= 1) {
        int u = (tid >= off) ? s[tid - off] : 0;
        __syncthreads();
        s[tid] += u;
        __syncthreads();
    }
    if (tid == 0) atomicExch(&g_bsum[b], s[SCAN_BLK - 1]);
    if (tid < 128) {
        int v = 0;
        if (tid < b) {
            int a;
            do { a = atomicAdd(&g_bsum[tid], 0); } while (a == -1);
            v = a;
        }
        bs[tid] = v;
    }
    __syncthreads();
    #pragma unroll
    for (int off = 64; off > 0; off >>= 1) {
        if (tid < off) bs[tid] += bs[tid + off];
        __syncthreads();
    }
    int boff = bs[0];
    if (i < NN) {
        int excl = s[tid] - c + boff;
        g_rowptr[i] = excl;
        g_cursor[i] = excl;
        g_counts[i] = 0;                      // restore invariant for next call
        if (i == NN - 1) g_rowptr[NN] = excl + c;
    }
}

// ---------------- scatter + weight prep (absorbs W.*M conversion) --------------
__global__ void k_scatter(const int* __restrict__ src, const int* __restrict__ dst,
                          const float* __restrict__ ew,
                          const float* __restrict__ W1, const float* __restrict__ W2,
                          const float* __restrict__ M1, const float* __restrict__ M2) {
    int e = blockIdx.x * blockDim.x + threadIdx.x;
    if (e < EE) {
        int d = dst[e];
        int pos = atomicAdd(&g_cursor[d], 1);
        g_epack[pos] = make_int2(src[e], __float_as_int(ew[e]));
    }
    const int S1 = TT * HID_F * 48;        // 49152
    const int S2 = TT * OUT_F * 64;        // 32768
    if (e < S1) {
        int t = e / (HID_F * 48);
        int rem = e % (HID_F * 48);
        int n = rem / 48, k2 = rem % 48;
        int i0 = (2 * k2) * HID_F + n;
        int i1 = i0 + HID_F;
        const float* m = M1 + (size_t)t * IN_F * HID_F;
        g_B1h[e] = pack_h2(W1[i0] * m[i0], W1[i1] * m[i1]);
    }
    if (e < S2) {
        int t = e / (OUT_F * 64);
        int rem = e % (OUT_F * 64);
        int n = rem / 64, k2 = rem % 64;
        int i0 = (2 * k2) * OUT_F + n;
        int i1 = i0 + OUT_F;
        const float* m = M2 + (size_t)t * HID_F * OUT_F;
        g_B2h[e] = pack_h2(W2[i0] * m[i0], W2[i1] * m[i1]);
    }
}

// ---------------- SpMM1: agg1h = spmm(xh), warp per node, 4-deep (regs=32) -----
// (R14 showed 8-deep costs regs 32->40 -> occupancy cliff; 4-deep is optimal.)
__device__ __forceinline__ void accx(float2& A0, float2& A1, uint2 u, float w) {
    float2 f;
    f = __half22float2(*(__half2*)&u.x); A0.x += w * f.x; A0.y += w * f.y;
    f = __half22float2(*(__half2*)&u.y); A1.x += w * f.x; A1.y += w * f.y;
}

__global__ void k_spmm96() {
    int warp = (blockIdx.x * blockDim.x + threadIdx.x) >> 5;
    int lane = threadIdx.x & 31;
    if (warp >= NN) return;
    int r0 = g_rowptr[warp], r1 = g_rowptr[warp + 1];
    const uint2* xh = (const uint2*)g_xh;     // 24 uint2 (8B) per 192B row
    const bool act = lane < 24;
    const uint2 z = make_uint2(0u, 0u);

    float2 A0 = make_float2(0.f, 0.f), A1 = make_float2(0.f, 0.f);
    int r = r0;
    for (; r + 3 < r1; r += 4) {
        int2 e0 = g_epack[r],     e1 = g_epack[r + 1];
        int2 e2 = g_epack[r + 2], e3 = g_epack[r + 3];
        uint2 u0 = act ? __ldg(&xh[e0.x * 24 + lane]) : z;
        uint2 u1 = act ? __ldg(&xh[e1.x * 24 + lane]) : z;
        uint2 u2 = act ? __ldg(&xh[e2.x * 24 + lane]) : z;
        uint2 u3 = act ? __ldg(&xh[e3.x * 24 + lane]) : z;
        accx(A0, A1, u0, __int_as_float(e0.y));
        accx(A0, A1, u1, __int_as_float(e1.y));
        accx(A0, A1, u2, __int_as_float(e2.y));
        accx(A0, A1, u3, __int_as_float(e3.y));
    }
    if (r + 1 < r1) {                       // 2-batch tail
        int2 e0 = g_epack[r], e1 = g_epack[r + 1];
        uint2 u0 = act ? __ldg(&xh[e0.x * 24 + lane]) : z;
        uint2 u1 = act ? __ldg(&xh[e1.x * 24 + lane]) : z;
        accx(A0, A1, u0, __int_as_float(e0.y));
        accx(A0, A1, u1, __int_as_float(e1.y));
        r += 2;
    }
    if (r < r1) {
        int2 e = g_epack[r];
        uint2 u = act ? __ldg(&xh[e.x * 24 + lane]) : z;
        accx(A0, A1, u, __int_as_float(e.y));
    }
    if (act) {
        uint2 o = make_uint2(pack_h2(A0.x, A0.y), pack_h2(A1.x, A1.y));
        ((uint2*)g_agg1h)[(size_t)warp * 24 + lane] = o;
    }
}

// ---------------- SpMM2: out[t,n,:] = spmm(p_t), 2 warps per node, unroll 8 ----
__device__ __forceinline__ void acc8u(float acc[8], uint4 u, float w) {
    const __half2* h = (const __half2*)&u;
    #pragma unroll
    for (int q = 0; q < 4; q++) {
        float2 f = __half22float2(h[q]);
        acc[2 * q]     += w * f.x;
        acc[2 * q + 1] += w * f.y;
    }
}

__global__ void k_spmm_all(float* __restrict__ out) {
    int gw   = (blockIdx.x * blockDim.x + threadIdx.x) >> 5;  // global warp
    int node = gw >> 1;
    int h    = gw & 1;                                         // channel half
    int lane = threadIdx.x & 31;
    if (node >= NN) return;
    int r0 = g_rowptr[node], r1 = g_rowptr[node + 1];

    const uint4* base = (const uint4*)g_ph;
    const int off = h * 32 + lane;

    float acc[8];
    #pragma unroll
    for (int i = 0; i < 8; i++) acc[i] = 0.f;

    int r = r0;
    for (; r + 7 < r1; r += 8) {                // 8-deep MLP main loop
        int2 e[8];
        #pragma unroll
        for (int q = 0; q < 8; q++) e[q] = g_epack[r + q];
        uint4 u[8];
        #pragma unroll
        for (int q = 0; q < 8; q++) u[q] = __ldg(&base[(size_t)e[q].x * 64 + off]);
        #pragma unroll
        for (int q = 0; q < 8; q++) acc8u(acc, u[q], __int_as_float(e[q].y));
    }
    if (r + 3 < r1) {                           // 4-batch tail
        int2 e[4];
        #pragma unroll
        for (int q = 0; q < 4; q++) e[q] = g_epack[r + q];
        uint4 u[4];
        #pragma unroll
        for (int q = 0; q < 4; q++) u[q] = __ldg(&base[(size_t)e[q].x * 64 + off]);
        #pragma unroll
        for (int q = 0; q < 4; q++) acc8u(acc, u[q], __int_as_float(e[q].y));
        r += 4;
    }
    if (r + 1 < r1) {                           // 2-batch tail
        int2 e0 = g_epack[r], e1 = g_epack[r + 1];
        uint4 u0 = __ldg(&base[(size_t)e0.x * 64 + off]);
        uint4 u1 = __ldg(&base[(size_t)e1.x * 64 + off]);
        acc8u(acc, u0, __int_as_float(e0.y));
        acc8u(acc, u1, __int_as_float(e1.y));
        r += 2;
    }
    if (r < r1) {
        int2 e = g_epack[r];
        uint4 u = __ldg(&base[(size_t)e.x * 64 + off]);
        acc8u(acc, u, __int_as_float(e.y));
    }

    int t  = 4 * h + (lane >> 3);
    int c0 = (lane & 7) * 8;
    float* op = out + ((size_t)t * NN + node) * OUT_F + c0;
    *(float4*)(op)     = make_float4(acc[0], acc[1], acc[2], acc[3]);
    *(float4*)(op + 4) = make_float4(acc[4], acc[5], acc[6], acc[7]);
}

// ---------------- fused fp16 mma GEMM (4 samples per CTA, grid.y=2) -----------
// smem uint32 (fp16x2) layout, padded lds for conflict-free fragment access:
//   A  128 rows x 48 k2, ld 52  @ 0       (6656)
//   B1 128 n    x 48 k2, ld 52  @ 6656    (6656)
//   B2 64  n    x 64 k2, ld 68  @ 13312   (4352)
//   H  128 rows x 64 k2, ld 68  @ 17664   (8704)
#define OFF_A   0
#define LDA     52
#define OFF_B1  6656
#define LDB1    52
#define OFF_B2  13312
#define LDB2    68
#define OFF_H   17664
#define LDH     68
#define FUSED_WORDS (OFF_H + 128 * LDH)            // 26368 words
#define FUSED_SMEM  (FUSED_WORDS * 4)              // 105472 bytes

__global__ void __launch_bounds__(256, 2)
k_fused_gemm() {
    extern __shared__ uint32_t sm[];
    const int tid  = threadIdx.x;
    const int wid  = tid >> 5;
    const int lane = tid & 31;
    const int gid  = lane >> 2;
    const int tig  = lane & 3;
    const int row0 = blockIdx.x * 128;
    const int tbase = blockIdx.y * 4;              // 4 MC samples per CTA

    // ---- stage A tile ONCE (fp16x2)
    const uint32_t* ah = (const uint32_t*)g_agg1h;
    for (int e = tid; e < 128 * 48; e += 256) {
        int r = e / 48, k2 = e % 48;
        int gr = row0 + r;
        sm[OFF_A + r * LDA + k2] = (gr < NN) ? ah[gr * 48 + k2] : 0u;
    }

    const int r0 = wid * 16;
    const int rowA = row0 + r0 + gid;
    const int rowB = rowA + 8;

    for (int ti = 0; ti < 4; ti++) {
        const int t = tbase + ti;
        __syncthreads();
        {
            const uint32_t* b1 = g_B1h + t * HID_F * 48;
            for (int e = tid; e < HID_F * 48; e += 256)
                sm[OFF_B1 + (e / 48) * LDB1 + (e % 48)] = b1[e];
            const uint32_t* b2 = g_B2h + t * OUT_F * 64;
            for (int e = tid; e < OUT_F * 64; e += 256)
                sm[OFF_B2 + (e >> 6) * LDB2 + (e & 63)] = b2[e];
        }
        __syncthreads();

        // ===== GEMM1: H[128,128] = A[128,96] @ B1, 6 k16-steps =====
        float acc1[16][4];
        #pragma unroll
        for (int j = 0; j < 16; j++)
            #pragma unroll
            for (int i = 0; i < 4; i++) acc1[j][i] = 0.f;

        #pragma unroll
        for (int kb = 0; kb < 6; kb++) {
            const int k2b = kb * 8;
            uint32_t a0 = sm[OFF_A + (r0 + gid)     * LDA + k2b + tig];
            uint32_t a1 = sm[OFF_A + (r0 + gid + 8) * LDA + k2b + tig];
            uint32_t a2 = sm[OFF_A + (r0 + gid)     * LDA + k2b + tig + 4];
            uint32_t a3 = sm[OFF_A + (r0 + gid + 8) * LDA + k2b + tig + 4];
            #pragma unroll
            for (int j = 0; j < 16; j++) {
                uint32_t b0 = sm[OFF_B1 + (j * 8 + gid) * LDB1 + k2b + tig];
                uint32_t b1 = sm[OFF_B1 + (j * 8 + gid) * LDB1 + k2b + tig + 4];
                mma_f16(acc1[j], a0, a1, a2, a3, b0, b1);
            }
        }

        // relu + fp16 pack, store H[row][k2] (warp-private rows)
        #pragma unroll
        for (int j = 0; j < 16; j++) {
            float f0 = acc1[j][0], f1 = acc1[j][1], f2 = acc1[j][2], f3 = acc1[j][3];
            uint32_t uA = pack_h2(f0 > 0.f ? f0 : 0.f, f1 > 0.f ? f1 : 0.f);
            uint32_t uB = pack_h2(f2 > 0.f ? f2 : 0.f, f3 > 0.f ? f3 : 0.f);
            sm[OFF_H + (r0 + gid)     * LDH + 4 * j + tig] = uA;
            sm[OFF_H + (r0 + gid + 8) * LDH + 4 * j + tig] = uB;
        }
        __syncwarp();

        // ===== GEMM2: P[128,64] = H[128,128] @ B2, 8 k16-steps =====
        float acc2[8][4];
        #pragma unroll
        for (int j = 0; j < 8; j++)
            #pragma unroll
            for (int i = 0; i < 4; i++) acc2[j][i] = 0.f;

        #pragma unroll
        for (int kb = 0; kb < 8; kb++) {
            const int k2b = kb * 8;
            uint32_t a0 = sm[OFF_H + (r0 + gid)     * LDH + k2b + tig];
            uint32_t a1 = sm[OFF_H + (r0 + gid + 8) * LDH + k2b + tig];
            uint32_t a2 = sm[OFF_H + (r0 + gid)     * LDH + k2b + tig + 4];
            uint32_t a3 = sm[OFF_H + (r0 + gid + 8) * LDH + k2b + tig + 4];
            #pragma unroll
            for (int j = 0; j < 8; j++) {
                uint32_t b0 = sm[OFF_B2 + (j * 8 + gid) * LDB2 + k2b + tig];
                uint32_t b1 = sm[OFF_B2 + (j * 8 + gid) * LDB2 + k2b + tig + 4];
                mma_f16(acc2[j], a0, a1, a2, a3, b0, b1);
            }
        }

        // ---- epilogue: write p tile as fp16 into g_ph[n][t*64+c]
        if (rowA < NN) {
            __half* p = g_ph + (size_t)rowA * 512 + t * 64;
            #pragma unroll
            for (int j = 0; j < 8; j++)
                *(uint32_t*)(p + j * 8 + 2 * tig) = pack_h2(acc2[j][0], acc2[j][1]);
        }
        if (rowB < NN) {
            __half* p = g_ph + (size_t)rowB * 512 + t * 64;
            #pragma unroll
            for (int j = 0; j < 8; j++)
                *(uint32_t*)(p + j * 8 + 2 * tig) = pack_h2(acc2[j][2], acc2[j][3]);
        }
    }
}

// ---------------- launch ------------------------------------------------------
extern "C" void kernel_launch(void* const* d_in, const int* in_sizes, int n_in,
                              void* d_out, int out_size) {
    (void)in_sizes; (void)n_in; (void)out_size;
    const float* x   = (const float*)d_in[0];
    const float* ew  = (const float*)d_in[1];
    const float* W1  = (const float*)d_in[2];
    const float* W2  = (const float*)d_in[3];
    const float* m1  = (const float*)d_in[4];
    const float* m2  = (const float*)d_in[5];
    const int*   src = (const int*)d_in[6];
    const int*   dst = (const int*)d_in[7];
    float* out = (float*)d_out;

    cudaFuncSetAttribute((const void*)k_fused_gemm,
                         cudaFuncAttributeMaxDynamicSharedMemorySize, FUSED_SMEM);

    // 1. front-end: x->fp16 (float4), degree hist, scan sentinel
    k_convert<<<(XW4 + 255) / 256, 256>>>(x, dst);
    // 2. single-kernel scan -> rowptr/cursor (+ counts re-zeroed)
    k_scan<<<NBLK, SCAN_BLK>>>();
    // 3. CSR scatter + W.*M fp16 prep (absorbed)
    k_scatter<<<(EE + 255) / 256, 256>>>(src, dst, ew, W1, W2, m1, m2);
    // 4. agg1h = spmm(xh), 4-deep pipeline (regs=32, occupancy-optimal)
    k_spmm96<<<(NN * 32 + 255) / 256, 256>>>();
    // 5. fused fp16 mma, 4 samples per CTA, grid.y=2
    dim3 gf((NN + 127) / 128, 2);
    k_fused_gemm<<<gf, 256, FUSED_SMEM>>>();
    // 6. out = spmm(p), 2 warps per node, 8-deep gather pipeline
    k_spmm_all<<<(NN * 2 * 32 + 255) / 256, 256>>>(out);
}

// round 17
// speedup vs baseline: 1.0130x; 1.0130x over previous
#include <cuda_runtime.h>
#include <cuda_fp16.h>
#include <cstdint>

// Problem constants (fixed by the dataset)
#define NN    50000
#define EE    800000
#define IN_F  96
#define HID_F 128
#define OUT_F 64
#define TT    8

#define SCAN_BLK 512
#define NBLK ((NN + SCAN_BLK - 1) / SCAN_BLK)    // 98

// ---------------- static device scratch (no allocations allowed) -------------
__device__ int      g_counts[NN];      // zero-init at load; re-zeroed by k_scan
__device__ int      g_rowptr[NN + 1];
__device__ int      g_cursor[NN];
__device__ int      g_bsum[NBLK];      // sentinel -1 written by k_convert each call
__device__ int2     g_epack[EE];                            // (src, w-as-bits)
__device__ __half   g_xh[(size_t)NN * IN_F];                // 9.6 MB fp16 x
__device__ __half   g_agg1h[(size_t)NN * IN_F];             // 9.6 MB fp16 agg1
__device__ __half   g_ph[(size_t)NN * TT * OUT_F];          // 51.2 MB, [n][t*64+c]
__device__ uint32_t g_B1h[TT * HID_F * 48];                 // fp16x2 [t][n][k2]
__device__ uint32_t g_B2h[TT * OUT_F * 64];                 // fp16x2 [t][n][k2]

// ---------------- helpers ------------------------------------------------------
__device__ __forceinline__ void mma_f16(float d[4],
                                        uint32_t a0, uint32_t a1, uint32_t a2, uint32_t a3,
                                        uint32_t b0, uint32_t b1) {
    asm volatile("mma.sync.aligned.m16n8k16.row.col.f32.f16.f16.f32 "
        "{%0,%1,%2,%3}, {%4,%5,%6,%7}, {%8,%9}, {%0,%1,%2,%3};"
        : "+f"(d[0]), "+f"(d[1]), "+f"(d[2]), "+f"(d[3])
        : "r"(a0), "r"(a1), "r"(a2), "r"(a3), "r"(b0), "r"(b1));
}
__device__ __forceinline__ uint32_t pack_h2(float a, float b) {
    __half2 h = __float22half2_rn(make_float2(a, b));
    return *(uint32_t*)&h;
}

// ---------------- convert + hist + sentinel (fused front-end) ------------------
#define XW4 (NN * IN_F / 4)                // 1,200,000 float4 granules (> EE ok)
__global__ void k_convert(const float* __restrict__ x,
                          const int* __restrict__ dst) {
    int i = blockIdx.x * blockDim.x + threadIdx.x;
    if (i < NBLK) g_bsum[i] = -1;                       // sentinel for k_scan
    if (i < EE) atomicAdd(&g_counts[dst[i]], 1);        // degree histogram
    if (i < XW4) {
        float4 v = ((const float4*)x)[i];
        uint2 o = make_uint2(pack_h2(v.x, v.y), pack_h2(v.z, v.w));
        ((uint2*)g_xh)[i] = o;
    }
}

// ---------------- single-kernel scan (aggregate exchange via sentinel) ---------
__global__ void k_scan() {
    __shared__ int s[SCAN_BLK];
    __shared__ int bs[128];
    int b = blockIdx.x, tid = threadIdx.x;
    int i = b * SCAN_BLK + tid;
    int c = (i < NN) ? g_counts[i] : 0;
    s[tid] = c;
    __syncthreads();
    #pragma unroll
    for (int off = 1; off < SCAN_BLK; off <<= 1) {
        int u = (tid >= off) ? s[tid - off] : 0;
        __syncthreads();
        s[tid] += u;
        __syncthreads();
    }
    if (tid == 0) atomicExch(&g_bsum[b], s[SCAN_BLK - 1]);
    if (tid < 128) {
        int v = 0;
        if (tid < b) {
            int a;
            do { a = atomicAdd(&g_bsum[tid], 0); } while (a == -1);
            v = a;
        }
        bs[tid] = v;
    }
    __syncthreads();
    #pragma unroll
    for (int off = 64; off > 0; off >>= 1) {
        if (tid < off) bs[tid] += bs[tid + off];
        __syncthreads();
    }
    int boff = bs[0];
    if (i < NN) {
        int excl = s[tid] - c + boff;
        g_rowptr[i] = excl;
        g_cursor[i] = excl;
        g_counts[i] = 0;                      // restore invariant for next call
        if (i == NN - 1) g_rowptr[NN] = excl + c;
    }
}

// ---------------- scatter + weight prep (absorbs W.*M conversion) --------------
__global__ void k_scatter(const int* __restrict__ src, const int* __restrict__ dst,
                          const float* __restrict__ ew,
                          const float* __restrict__ W1, const float* __restrict__ W2,
                          const float* __restrict__ M1, const float* __restrict__ M2) {
    int e = blockIdx.x * blockDim.x + threadIdx.x;
    if (e < EE) {
        int d = dst[e];
        int pos = atomicAdd(&g_cursor[d], 1);
        g_epack[pos] = make_int2(src[e], __float_as_int(ew[e]));
    }
    const int S1 = TT * HID_F * 48;        // 49152
    const int S2 = TT * OUT_F * 64;        // 32768
    if (e < S1) {
        int t = e / (HID_F * 48);
        int rem = e % (HID_F * 48);
        int n = rem / 48, k2 = rem % 48;
        int i0 = (2 * k2) * HID_F + n;
        int i1 = i0 + HID_F;
        const float* m = M1 + (size_t)t * IN_F * HID_F;
        g_B1h[e] = pack_h2(W1[i0] * m[i0], W1[i1] * m[i1]);
    }
    if (e < S2) {
        int t = e / (OUT_F * 64);
        int rem = e % (OUT_F * 64);
        int n = rem / 64, k2 = rem % 64;
        int i0 = (2 * k2) * OUT_F + n;
        int i1 = i0 + OUT_F;
        const float* m = M2 + (size_t)t * HID_F * OUT_F;
        g_B2h[e] = pack_h2(W2[i0] * m[i0], W2[i1] * m[i1]);
    }
}

// ---------------- SpMM1: agg1h = spmm(xh), warp per node, 4-deep (regs=32) -----
// (R14 showed 8-deep costs regs 32->40 -> occupancy cliff; 4-deep is optimal.
//  R16 showed __ldg is neutral-to-negative; plain LDG is the measured optimum.)
__device__ __forceinline__ void accx(float2& A0, float2& A1, uint2 u, float w) {
    float2 f;
    f = __half22float2(*(__half2*)&u.x); A0.x += w * f.x; A0.y += w * f.y;
    f = __half22float2(*(__half2*)&u.y); A1.x += w * f.x; A1.y += w * f.y;
}

__global__ void k_spmm96() {
    int warp = (blockIdx.x * blockDim.x + threadIdx.x) >> 5;
    int lane = threadIdx.x & 31;
    if (warp >= NN) return;
    int r0 = g_rowptr[warp], r1 = g_rowptr[warp + 1];
    const uint2* xh = (const uint2*)g_xh;     // 24 uint2 (8B) per 192B row
    const bool act = lane < 24;
    const uint2 z = make_uint2(0u, 0u);

    float2 A0 = make_float2(0.f, 0.f), A1 = make_float2(0.f, 0.f);
    int r = r0;
    for (; r + 3 < r1; r += 4) {
        int2 e0 = g_epack[r],     e1 = g_epack[r + 1];
        int2 e2 = g_epack[r + 2], e3 = g_epack[r + 3];
        uint2 u0 = act ? xh[e0.x * 24 + lane] : z;
        uint2 u1 = act ? xh[e1.x * 24 + lane] : z;
        uint2 u2 = act ? xh[e2.x * 24 + lane] : z;
        uint2 u3 = act ? xh[e3.x * 24 + lane] : z;
        accx(A0, A1, u0, __int_as_float(e0.y));
        accx(A0, A1, u1, __int_as_float(e1.y));
        accx(A0, A1, u2, __int_as_float(e2.y));
        accx(A0, A1, u3, __int_as_float(e3.y));
    }
    if (r + 1 < r1) {                       // 2-batch tail
        int2 e0 = g_epack[r], e1 = g_epack[r + 1];
        uint2 u0 = act ? xh[e0.x * 24 + lane] : z;
        uint2 u1 = act ? xh[e1.x * 24 + lane] : z;
        accx(A0, A1, u0, __int_as_float(e0.y));
        accx(A0, A1, u1, __int_as_float(e1.y));
        r += 2;
    }
    if (r < r1) {
        int2 e = g_epack[r];
        uint2 u = act ? xh[e.x * 24 + lane] : z;
        accx(A0, A1, u, __int_as_float(e.y));
    }
    if (act) {
        uint2 o = make_uint2(pack_h2(A0.x, A0.y), pack_h2(A1.x, A1.y));
        ((uint2*)g_agg1h)[(size_t)warp * 24 + lane] = o;
    }
}

// ---------------- SpMM2: out[t,n,:] = spmm(p_t), 2 warps per node, unroll 8 ----
__device__ __forceinline__ void acc8u(float acc[8], uint4 u, float w) {
    const __half2* h = (const __half2*)&u;
    #pragma unroll
    for (int q = 0; q < 4; q++) {
        float2 f = __half22float2(h[q]);
        acc[2 * q]     += w * f.x;
        acc[2 * q + 1] += w * f.y;
    }
}

__global__ void k_spmm_all(float* __restrict__ out) {
    int gw   = (blockIdx.x * blockDim.x + threadIdx.x) >> 5;  // global warp
    int node = gw >> 1;
    int h    = gw & 1;                                         // channel half
    int lane = threadIdx.x & 31;
    if (node >= NN) return;
    int r0 = g_rowptr[node], r1 = g_rowptr[node + 1];

    const uint4* base = (const uint4*)g_ph;
    const int off = h * 32 + lane;

    float acc[8];
    #pragma unroll
    for (int i = 0; i < 8; i++) acc[i] = 0.f;

    int r = r0;
    for (; r + 7 < r1; r += 8) {                // 8-deep MLP main loop
        int2 e[8];
        #pragma unroll
        for (int q = 0; q < 8; q++) e[q] = g_epack[r + q];
        uint4 u[8];
        #pragma unroll
        for (int q = 0; q < 8; q++) u[q] = base[(size_t)e[q].x * 64 + off];
        #pragma unroll
        for (int q = 0; q < 8; q++) acc8u(acc, u[q], __int_as_float(e[q].y));
    }
    if (r + 3 < r1) {                           // 4-batch tail
        int2 e[4];
        #pragma unroll
        for (int q = 0; q < 4; q++) e[q] = g_epack[r + q];
        uint4 u[4];
        #pragma unroll
        for (int q = 0; q < 4; q++) u[q] = base[(size_t)e[q].x * 64 + off];
        #pragma unroll
        for (int q = 0; q < 4; q++) acc8u(acc, u[q], __int_as_float(e[q].y));
        r += 4;
    }
    if (r + 1 < r1) {                           // 2-batch tail
        int2 e0 = g_epack[r], e1 = g_epack[r + 1];
        uint4 u0 = base[(size_t)e0.x * 64 + off];
        uint4 u1 = base[(size_t)e1.x * 64 + off];
        acc8u(acc, u0, __int_as_float(e0.y));
        acc8u(acc, u1, __int_as_float(e1.y));
        r += 2;
    }
    if (r < r1) {
        int2 e = g_epack[r];
        uint4 u = base[(size_t)e.x * 64 + off];
        acc8u(acc, u, __int_as_float(e.y));
    }

    int t  = 4 * h + (lane >> 3);
    int c0 = (lane & 7) * 8;
    float* op = out + ((size_t)t * NN + node) * OUT_F + c0;
    *(float4*)(op)     = make_float4(acc[0], acc[1], acc[2], acc[3]);
    *(float4*)(op + 4) = make_float4(acc[4], acc[5], acc[6], acc[7]);
}

// ---------------- fused fp16 mma GEMM (4 samples per CTA, grid.y=2) -----------
// smem uint32 (fp16x2) layout, padded lds for conflict-free fragment access:
//   A  128 rows x 48 k2, ld 52  @ 0       (6656)
//   B1 128 n    x 48 k2, ld 52  @ 6656    (6656)
//   B2 64  n    x 64 k2, ld 68  @ 13312   (4352)
//   H  128 rows x 64 k2, ld 68  @ 17664   (8704)
#define OFF_A   0
#define LDA     52
#define OFF_B1  6656
#define LDB1    52
#define OFF_B2  13312
#define LDB2    68
#define OFF_H   17664
#define LDH     68
#define FUSED_WORDS (OFF_H + 128 * LDH)            // 26368 words
#define FUSED_SMEM  (FUSED_WORDS * 4)              // 105472 bytes

__global__ void __launch_bounds__(256, 2)
k_fused_gemm() {
    extern __shared__ uint32_t sm[];
    const int tid  = threadIdx.x;
    const int wid  = tid >> 5;
    const int lane = tid & 31;
    const int gid  = lane >> 2;
    const int tig  = lane & 3;
    const int row0 = blockIdx.x * 128;
    const int tbase = blockIdx.y * 4;              // 4 MC samples per CTA

    // ---- stage A tile ONCE (fp16x2)
    const uint32_t* ah = (const uint32_t*)g_agg1h;
    for (int e = tid; e < 128 * 48; e += 256) {
        int r = e / 48, k2 = e % 48;
        int gr = row0 + r;
        sm[OFF_A + r * LDA + k2] = (gr < NN) ? ah[gr * 48 + k2] : 0u;
    }

    const int r0 = wid * 16;
    const int rowA = row0 + r0 + gid;
    const int rowB = rowA + 8;

    for (int ti = 0; ti < 4; ti++) {
        const int t = tbase + ti;
        __syncthreads();
        {
            const uint32_t* b1 = g_B1h + t * HID_F * 48;
            for (int e = tid; e < HID_F * 48; e += 256)
                sm[OFF_B1 + (e / 48) * LDB1 + (e % 48)] = b1[e];
            const uint32_t* b2 = g_B2h + t * OUT_F * 64;
            for (int e = tid; e < OUT_F * 64; e += 256)
                sm[OFF_B2 + (e >> 6) * LDB2 + (e & 63)] = b2[e];
        }
        __syncthreads();

        // ===== GEMM1: H[128,128] = A[128,96] @ B1, 6 k16-steps =====
        float acc1[16][4];
        #pragma unroll
        for (int j = 0; j < 16; j++)
            #pragma unroll
            for (int i = 0; i < 4; i++) acc1[j][i] = 0.f;

        #pragma unroll
        for (int kb = 0; kb < 6; kb++) {
            const int k2b = kb * 8;
            uint32_t a0 = sm[OFF_A + (r0 + gid)     * LDA + k2b + tig];
            uint32_t a1 = sm[OFF_A + (r0 + gid + 8) * LDA + k2b + tig];
            uint32_t a2 = sm[OFF_A + (r0 + gid)     * LDA + k2b + tig + 4];
            uint32_t a3 = sm[OFF_A + (r0 + gid + 8) * LDA + k2b + tig + 4];
            #pragma unroll
            for (int j = 0; j < 16; j++) {
                uint32_t b0 = sm[OFF_B1 + (j * 8 + gid) * LDB1 + k2b + tig];
                uint32_t b1 = sm[OFF_B1 + (j * 8 + gid) * LDB1 + k2b + tig + 4];
                mma_f16(acc1[j], a0, a1, a2, a3, b0, b1);
            }
        }

        // relu + fp16 pack, store H[row][k2] (warp-private rows)
        #pragma unroll
        for (int j = 0; j < 16; j++) {
            float f0 = acc1[j][0], f1 = acc1[j][1], f2 = acc1[j][2], f3 = acc1[j][3];
            uint32_t uA = pack_h2(f0 > 0.f ? f0 : 0.f, f1 > 0.f ? f1 : 0.f);
            uint32_t uB = pack_h2(f2 > 0.f ? f2 : 0.f, f3 > 0.f ? f3 : 0.f);
            sm[OFF_H + (r0 + gid)     * LDH + 4 * j + tig] = uA;
            sm[OFF_H + (r0 + gid + 8) * LDH + 4 * j + tig] = uB;
        }
        __syncwarp();

        // ===== GEMM2: P[128,64] = H[128,128] @ B2, 8 k16-steps =====
        float acc2[8][4];
        #pragma unroll
        for (int j = 0; j < 8; j++)
            #pragma unroll
            for (int i = 0; i < 4; i++) acc2[j][i] = 0.f;

        #pragma unroll
        for (int kb = 0; kb < 8; kb++) {
            const int k2b = kb * 8;
            uint32_t a0 = sm[OFF_H + (r0 + gid)     * LDH + k2b + tig];
            uint32_t a1 = sm[OFF_H + (r0 + gid + 8) * LDH + k2b + tig];
            uint32_t a2 = sm[OFF_H + (r0 + gid)     * LDH + k2b + tig + 4];
            uint32_t a3 = sm[OFF_H + (r0 + gid + 8) * LDH + k2b + tig + 4];
            #pragma unroll
            for (int j = 0; j < 8; j++) {
                uint32_t b0 = sm[OFF_B2 + (j * 8 + gid) * LDB2 + k2b + tig];
                uint32_t b1 = sm[OFF_B2 + (j * 8 + gid) * LDB2 + k2b + tig + 4];
                mma_f16(acc2[j], a0, a1, a2, a3, b0, b1);
            }
        }

        // ---- epilogue: write p tile as fp16 into g_ph[n][t*64+c]
        if (rowA < NN) {
            __half* p = g_ph + (size_t)rowA * 512 + t * 64;
            #pragma unroll
            for (int j = 0; j < 8; j++)
                *(uint32_t*)(p + j * 8 + 2 * tig) = pack_h2(acc2[j][0], acc2[j][1]);
        }
        if (rowB < NN) {
            __half* p = g_ph + (size_t)rowB * 512 + t * 64;
            #pragma unroll
            for (int j = 0; j < 8; j++)
                *(uint32_t*)(p + j * 8 + 2 * tig) = pack_h2(acc2[j][2], acc2[j][3]);
        }
    }
}

// ---------------- launch ------------------------------------------------------
extern "C" void kernel_launch(void* const* d_in, const int* in_sizes, int n_in,
                              void* d_out, int out_size) {
    (void)in_sizes; (void)n_in; (void)out_size;
    const float* x   = (const float*)d_in[0];
    const float* ew  = (const float*)d_in[1];
    const float* W1  = (const float*)d_in[2];
    const float* W2  = (const float*)d_in[3];
    const float* m1  = (const float*)d_in[4];
    const float* m2  = (const float*)d_in[5];
    const int*   src = (const int*)d_in[6];
    const int*   dst = (const int*)d_in[7];
    float* out = (float*)d_out;

    cudaFuncSetAttribute((const void*)k_fused_gemm,
                         cudaFuncAttributeMaxDynamicSharedMemorySize, FUSED_SMEM);

    // 1. front-end: x->fp16 (float4), degree hist, scan sentinel
    k_convert<<<(XW4 + 255) / 256, 256>>>(x, dst);
    // 2. single-kernel scan -> rowptr/cursor (+ counts re-zeroed)
    k_scan<<<NBLK, SCAN_BLK>>>();
    // 3. CSR scatter + W.*M fp16 prep (absorbed)
    k_scatter<<<(EE + 255) / 256, 256>>>(src, dst, ew, W1, W2, m1, m2);
    // 4. agg1h = spmm(xh), 4-deep pipeline (regs=32, occupancy-optimal)
    k_spmm96<<<(NN * 32 + 255) / 256, 256>>>();
    // 5. fused fp16 mma, 4 samples per CTA, grid.y=2
    dim3 gf((NN + 127) / 128, 2);
    k_fused_gemm<<<gf, 256, FUSED_SMEM>>>();
    // 6. out = spmm(p), 2 warps per node, 8-deep gather pipeline
    k_spmm_all<<<(NN * 2 * 32 + 255) / 256, 256>>>(out);
}